// round 17
// baseline (speedup 1.0000x reference)
#include <cuda_runtime.h>
#include <cuda_fp16.h>
#include <math.h>
#include <stdint.h>

using f16 = __half;

// Problem dims
#define BB   16
#define CC   192
#define HW   2304          // 48*48
#define NTOT (BB*HW)       // 36864
#define NB3  18            // K3 n-blocks per row (HW/128)

#define BM 128
#define ST 40              // smem row stride in halves (BK=32 tiles)
#define ST64 72            // smem row stride in halves (BK=64 tiles, 144B)

// ------------------------------------------------------------------
// Scratch (device globals -- allocation-free rule)
// ------------------------------------------------------------------
__device__ f16   g_xn_h[(size_t)NTOT * CC];
__device__ f16   g_xn_l[(size_t)NTOT * CC];
__device__ f16   g_q_h [(size_t)NTOT * CC];
__device__ f16   g_k_h [(size_t)NTOT * CC];
__device__ f16   g_vt_h[(size_t)CC * NTOT];    // Vt [192, 36864]
__device__ f16   g_w_h [(size_t)3 * CC * CC];
__device__ float g_s   [(size_t)BB * HW * HW]; // scores fp32
__device__ float g_part[(size_t)NTOT * NB3];   // per-row exp partial sums

// ------------------------------------------------------------------
// helpers
// ------------------------------------------------------------------
__device__ __forceinline__ uint32_t smem_to_u32(const void* p) {
    uint32_t a;
    asm("{ .reg .u64 t; cvta.to.shared.u64 t, %1; cvt.u32.u64 %0, t; }"
        : "=r"(a) : "l"(p));
    return a;
}

#define CP_ASYNC16(saddr, gptr) \
    asm volatile("cp.async.cg.shared.global [%0], [%1], 16;" \
        :: "r"(saddr), "l"(gptr) : "memory")
#define CP_COMMIT() asm volatile("cp.async.commit_group;" ::: "memory")
#define CP_WAIT1()  asm volatile("cp.async.wait_group 1;" ::: "memory")
#define CP_WAIT0()  asm volatile("cp.async.wait_group 0;" ::: "memory")

__device__ __forceinline__ void ldsm_x4(uint32_t addr, uint32_t& r0, uint32_t& r1,
                                        uint32_t& r2, uint32_t& r3) {
    asm volatile("ldmatrix.sync.aligned.m8n8.x4.shared.b16 {%0,%1,%2,%3}, [%4];"
        : "=r"(r0), "=r"(r1), "=r"(r2), "=r"(r3) : "r"(addr));
}

__device__ __forceinline__ void mma_f16(float* d, const uint32_t* a, const uint32_t* b) {
    asm volatile(
        "mma.sync.aligned.m16n8k16.row.col.f32.f16.f16.f32 "
        "{%0,%1,%2,%3}, {%4,%5,%6,%7}, {%8,%9}, {%0,%1,%2,%3};"
        : "+f"(d[0]), "+f"(d[1]), "+f"(d[2]), "+f"(d[3])
        : "r"(a[0]), "r"(a[1]), "r"(a[2]), "r"(a[3]), "r"(b[0]), "r"(b[1]));
}

__device__ __forceinline__ void split_f16(float v, f16& h, f16& l) {
    h = __float2half_rn(v);
    l = __float2half_rn(v - __half2float(h));
}
__device__ __forceinline__ uint32_t pack2h(f16 a, f16 b) {
    uint32_t u;
    asm("mov.b32 %0, {%1, %2};" : "=r"(u) : "h"(*(uint16_t*)&a), "h"(*(uint16_t*)&b));
    return u;
}

// ------------------------------------------------------------------
// K1: LayerNorm over C with [B,C,HW] -> [B,N,C], split hi/lo fp16
// ------------------------------------------------------------------
__global__ __launch_bounds__(256) void ln_transpose_kernel(
    const float* __restrict__ x,
    const float* __restrict__ ln_w,
    const float* __restrict__ ln_b,
    f16* __restrict__ xn_h, f16* __restrict__ xn_l)
{
    __shared__ float tile[CC][33];
    __shared__ float part_s[8][32];
    __shared__ float part_q[8][32];
    __shared__ float s_mu[32], s_ri[32];

    const int b  = blockIdx.y;
    const int n0 = blockIdx.x * 32;
    const int tid = threadIdx.x;
    const int n   = tid & 31;
    const int g   = tid >> 5;

    const float* xb = x + (size_t)b * CC * HW;

    #pragma unroll
    for (int i = 0; i < 24; i++) {
        int c = g + 8 * i;
        tile[c][n] = xb[(size_t)c * HW + n0 + n];
    }
    __syncthreads();

    float s = 0.f, q = 0.f;
    #pragma unroll
    for (int j = 0; j < 24; j++) {
        float v = tile[g + 8 * j][n];
        s += v; q += v * v;
    }
    part_s[g][n] = s;
    part_q[g][n] = q;
    __syncthreads();

    if (tid < 32) {
        float ts = 0.f, tq = 0.f;
        #pragma unroll
        for (int j = 0; j < 8; j++) { ts += part_s[j][tid]; tq += part_q[j][tid]; }
        float mu  = ts * (1.0f / CC);
        float var = tq * (1.0f / CC) - mu * mu;
        s_mu[tid] = mu;
        s_ri[tid] = rsqrtf(var + 1e-5f);
    }
    __syncthreads();

    #pragma unroll
    for (int i = 0; i < 24; i++) {
        int j  = tid + 256 * i;
        int c  = j % CC;
        int nn = j / CC;
        float v = (tile[c][nn] - s_mu[nn]) * s_ri[nn] * ln_w[c] + ln_b[c];
        f16 h, l; split_f16(v, h, l);
        size_t o = ((size_t)(b * HW + n0 + nn)) * CC + c;
        xn_h[o] = h; xn_l[o] = l;
    }
}

// ------------------------------------------------------------------
// Weight convert kernel (hi only)
// ------------------------------------------------------------------
__global__ __launch_bounds__(256) void wsplit_kernel(
    const float* __restrict__ Wq, const float* __restrict__ Wk,
    const float* __restrict__ Wv,
    f16* __restrict__ wh)
{
    int i = blockIdx.x * 256 + threadIdx.x;
    if (i >= 3 * CC * CC) return;
    int wsel = i / (CC * CC);
    int j    = i % (CC * CC);
    const float* W = (wsel == 0) ? Wq : (wsel == 1) ? Wk : Wv;
    wh[i] = __float2half_rn(W[j]);
}

// ------------------------------------------------------------------
// K2 GEMM (2-term), BN=192 full-width, BK=64, Q/K/V in one launch.
// 512 threads = 16 warps (4m x 4n), warp tile 32x48, 3 chunks.
// wsel 0/1 -> row-major fp16 out (Q/K); wsel 2 -> transposed out (Vt).
// ------------------------------------------------------------------
__global__ __launch_bounds__(512, 1) void gemm_qkv192(
    const f16* __restrict__ Ah, const f16* __restrict__ Al,
    const f16* __restrict__ Wh,
    f16* __restrict__ Q, f16* __restrict__ Kout, f16* __restrict__ Vt)
{
    extern __shared__ char smem[];
    const uint32_t sb = smem_to_u32(smem);

    constexpr int STAGE_H = (256 + 192) * ST64;  // 32256 halves
    constexpr int SLOTS   = 7;                   // 3584 units / 512 thr

    const int tid  = threadIdx.x;
    const int wid  = tid >> 5;
    const int lane = tid & 31;
    const int wm   = wid & 3;
    const int wn   = wid >> 2;
    const int m0   = blockIdx.x * BM;
    const int wsel = blockIdx.y;

    const f16* Bw = Wh + (size_t)wsel * CC * CC;

    const f16* gbase[SLOTS];
    uint32_t   soff[SLOTS];
    #pragma unroll
    for (int s = 0; s < SLOTS; s++) {
        int idx = s * 512 + tid;
        if (idx < 2048) {                       // A region (hi, lo): 256 rows x 8 units
            int arr = idx >> 10;
            int r   = (idx >> 3) & 127;
            int qd  = idx & 7;
            gbase[s] = (arr ? Al : Ah) + (size_t)(m0 + r) * CC + qd * 8;
            soff[s]  = arr * 128 * ST64 + r * ST64 + qd * 8;
        } else {                                // B region: 192 rows x 8 units
            int j = idx - 2048;
            int r = j >> 3, qd = j & 7;
            gbase[s] = Bw + (size_t)r * CC + qd * 8;
            soff[s]  = 256 * ST64 + r * ST64 + qd * 8;
        }
    }

    const int a_row = wm * 32 + (lane & 15);
    const int a_col = (lane >> 4) << 3;
    const int b_row = wn * 48 + ((lane >> 4) << 3) + (lane & 7);
    const int b_col = ((lane >> 3) & 1) << 3;

    float acc[2][6][4];
    #pragma unroll
    for (int i = 0; i < 2; i++)
        #pragma unroll
        for (int j = 0; j < 6; j++)
            #pragma unroll
            for (int t = 0; t < 4; t++) acc[i][j][t] = 0.f;

    const int nc = CC >> 6;   // 3

    #pragma unroll
    for (int s = 0; s < SLOTS; s++)
        CP_ASYNC16(sb + 2 * soff[s], gbase[s]);
    CP_COMMIT();

    for (int c = 0; c < nc; c++) {
        if (c + 1 < nc) {
            const int st = (c + 1) & 1;
            const int k0 = (c + 1) << 6;
            #pragma unroll
            for (int s = 0; s < SLOTS; s++)
                CP_ASYNC16(sb + 2 * (st * STAGE_H + soff[s]), gbase[s] + k0);
            CP_COMMIT();
            CP_WAIT1();
        } else {
            CP_WAIT0();
        }
        __syncthreads();

        const uint32_t stg = (c & 1) * STAGE_H;
        const uint32_t sAh = sb + 2 * (stg + 0);
        const uint32_t sAl = sb + 2 * (stg + 128 * ST64);
        const uint32_t sBh = sb + 2 * (stg + 256 * ST64);

        #pragma unroll
        for (int ks = 0; ks < 4; ks++) {
            const int kof = ks * 16;
            uint32_t ah[2][4], al[2][4], bh[3][4];
            #pragma unroll
            for (int mt = 0; mt < 2; mt++) {
                uint32_t off = 2 * ((a_row + mt * 16) * ST64 + kof + a_col);
                ldsm_x4(sAh + off, ah[mt][0], ah[mt][1], ah[mt][2], ah[mt][3]);
                ldsm_x4(sAl + off, al[mt][0], al[mt][1], al[mt][2], al[mt][3]);
            }
            #pragma unroll
            for (int nt2 = 0; nt2 < 3; nt2++) {
                uint32_t off = 2 * ((b_row + nt2 * 16) * ST64 + kof + b_col);
                ldsm_x4(sBh + off, bh[nt2][0], bh[nt2][1], bh[nt2][2], bh[nt2][3]);
            }
            #pragma unroll
            for (int mt = 0; mt < 2; mt++)
                #pragma unroll
                for (int nt = 0; nt < 6; nt++)
                    mma_f16(acc[mt][nt], ah[mt], &bh[nt >> 1][(nt & 1) * 2]);
            #pragma unroll
            for (int mt = 0; mt < 2; mt++)
                #pragma unroll
                for (int nt = 0; nt < 6; nt++)
                    mma_f16(acc[mt][nt], al[mt], &bh[nt >> 1][(nt & 1) * 2]);
        }
        __syncthreads();
    }

    constexpr int TS2 = 193;
    float* tile = (float*)smem;
    const int tr = lane >> 2;
    const int tc = (lane & 3) * 2;
    #pragma unroll
    for (int mt = 0; mt < 2; mt++) {
        #pragma unroll
        for (int nt = 0; nt < 6; nt++) {
            int rbase = wm * 32 + mt * 16 + tr;
            int cbase = wn * 48 + nt * 8 + tc;
            tile[rbase * TS2 + cbase]           = acc[mt][nt][0];
            tile[rbase * TS2 + cbase + 1]       = acc[mt][nt][1];
            tile[(rbase + 8) * TS2 + cbase]     = acc[mt][nt][2];
            tile[(rbase + 8) * TS2 + cbase + 1] = acc[mt][nt][3];
        }
    }
    __syncthreads();

    if (wsel < 2) {
        f16* Ch = wsel ? Kout : Q;
        #pragma unroll
        for (int it = 0; it < 24; it++) {
            int idx = tid + 512 * it;
            int r = idx / 96, p = idx % 96;
            f16 h0 = __float2half_rn(tile[r * TS2 + 2 * p]);
            f16 h1 = __float2half_rn(tile[r * TS2 + 2 * p + 1]);
            size_t o = (size_t)(m0 + r) * CC + 2 * p;
            *(uint32_t*)&Ch[o] = pack2h(h0, h1);
        }
    } else {
        #pragma unroll
        for (int it = 0; it < 24; it++) {
            int idx = tid + 512 * it;
            int r = idx >> 6, p = idx & 63;
            f16 h0 = __float2half_rn(tile[(2 * p) * TS2 + r]);
            f16 h1 = __float2half_rn(tile[(2 * p + 1) * TS2 + r]);
            size_t o = (size_t)r * NTOT + m0 + 2 * p;
            *(uint32_t*)&Vt[o] = pack2h(h0, h1);
        }
    }
}

// ------------------------------------------------------------------
// K3 GEMM (1-term fp16), 128x128, BK=64.
// Epilogue: fp32 S out + parallel exp partials.
// ------------------------------------------------------------------
__global__ __launch_bounds__(256) void gemm_qk128(
    const f16* __restrict__ Ah, int lda, size_t sA,
    const f16* __restrict__ Bh, int ldb, size_t sB,
    float* __restrict__ Cf, float* __restrict__ extra,
    int ldc, size_t sC, int K)
{
    extern __shared__ char smem[];
    const uint32_t sb = smem_to_u32(smem);

    constexpr int STAGE_H = 256 * ST64;
    constexpr int SLOTS   = 8;
    constexpr int TS3     = 132;

    const int tid  = threadIdx.x;
    const int wid  = tid >> 5;
    const int lane = tid & 31;
    const int wm   = wid & 3;
    const int wn   = wid >> 2;
    const int m0   = blockIdx.x * BM;
    const int n0   = blockIdx.y * 128;
    const int b    = blockIdx.z;

    Ah += (size_t)b * sA;
    Bh += (size_t)b * sB;

    const f16* gbase[SLOTS];
    uint32_t   soff[SLOTS];
    #pragma unroll
    for (int s = 0; s < SLOTS; s++) {
        int idx = s * 256 + tid;
        if (idx < 1024) {
            int r = idx >> 3, qd = idx & 7;
            gbase[s] = Ah + (size_t)(m0 + r) * lda + qd * 8;
            soff[s]  = r * ST64 + qd * 8;
        } else {
            int j = idx - 1024;
            int r = j >> 3, qd = j & 7;
            gbase[s] = Bh + (size_t)(n0 + r) * ldb + qd * 8;
            soff[s]  = 128 * ST64 + r * ST64 + qd * 8;
        }
    }

    const int a_row = wm * 32 + (lane & 15);
    const int a_col = (lane >> 4) << 3;
    const int b_row = wn * 64 + ((lane >> 4) << 3) + (lane & 7);
    const int b_col = ((lane >> 3) & 1) << 3;

    float acc[2][8][4];
    #pragma unroll
    for (int i = 0; i < 2; i++)
        #pragma unroll
        for (int j = 0; j < 8; j++)
            #pragma unroll
            for (int t = 0; t < 4; t++) acc[i][j][t] = 0.f;

    const int nc = K >> 6;

    #pragma unroll
    for (int s = 0; s < SLOTS; s++)
        CP_ASYNC16(sb + 2 * soff[s], gbase[s]);
    CP_COMMIT();

    for (int c = 0; c < nc; c++) {
        if (c + 1 < nc) {
            const int st = (c + 1) & 1;
            const int k0 = (c + 1) << 6;
            #pragma unroll
            for (int s = 0; s < SLOTS; s++)
                CP_ASYNC16(sb + 2 * (st * STAGE_H + soff[s]), gbase[s] + k0);
            CP_COMMIT();
            CP_WAIT1();
        } else {
            CP_WAIT0();
        }
        __syncthreads();

        const uint32_t stg = (c & 1) * STAGE_H;
        const uint32_t sA2 = sb + 2 * stg;
        const uint32_t sB2 = sb + 2 * (stg + 128 * ST64);

        #pragma unroll
        for (int ks = 0; ks < 4; ks++) {
            const int kof = ks * 16;
            uint32_t ah[2][4], bh[4][4];
            #pragma unroll
            for (int mt = 0; mt < 2; mt++) {
                uint32_t off = 2 * ((a_row + mt * 16) * ST64 + kof + a_col);
                ldsm_x4(sA2 + off, ah[mt][0], ah[mt][1], ah[mt][2], ah[mt][3]);
            }
            #pragma unroll
            for (int nt2 = 0; nt2 < 4; nt2++) {
                uint32_t off = 2 * ((b_row + nt2 * 16) * ST64 + kof + b_col);
                ldsm_x4(sB2 + off, bh[nt2][0], bh[nt2][1], bh[nt2][2], bh[nt2][3]);
            }
            #pragma unroll
            for (int mt = 0; mt < 2; mt++)
                #pragma unroll
                for (int nt = 0; nt < 8; nt++)
                    mma_f16(acc[mt][nt], ah[mt], &bh[nt >> 1][(nt & 1) * 2]);
        }
        __syncthreads();
    }

    float* tile = (float*)smem;
    const int tr = lane >> 2;
    const int tc = (lane & 3) * 2;
    #pragma unroll
    for (int mt = 0; mt < 2; mt++) {
        #pragma unroll
        for (int nt = 0; nt < 8; nt++) {
            int rbase = wm * 32 + mt * 16 + tr;
            int cbase = wn * 64 + nt * 8 + tc;
            tile[rbase * TS3 + cbase]           = acc[mt][nt][0];
            tile[rbase * TS3 + cbase + 1]       = acc[mt][nt][1];
            tile[(rbase + 8) * TS3 + cbase]     = acc[mt][nt][2];
            tile[(rbase + 8) * TS3 + cbase + 1] = acc[mt][nt][3];
        }
    }
    __syncthreads();

    Cf += (size_t)b * sC;
    #pragma unroll
    for (int it = 0; it < 16; it++) {
        int idx = tid + 256 * it;
        int r = idx >> 5, q = idx & 31;
        float4 v = make_float4(tile[r * TS3 + q * 4], tile[r * TS3 + q * 4 + 1],
                               tile[r * TS3 + q * 4 + 2], tile[r * TS3 + q * 4 + 3]);
        *(float4*)&Cf[(size_t)(m0 + r) * ldc + n0 + q * 4] = v;
    }

    {
        const int row = tid >> 1;
        const int c0  = (tid & 1) * 64;
        const float* tr0 = &tile[row * TS3 + c0];
        float s0 = 0.f, s1 = 0.f, s2 = 0.f, s3 = 0.f;
        #pragma unroll
        for (int j = 0; j < 64; j += 4) {
            s0 += __expf(tr0[j]);
            s1 += __expf(tr0[j + 1]);
            s2 += __expf(tr0[j + 2]);
            s3 += __expf(tr0[j + 3]);
        }
        float sum = (s0 + s1) + (s2 + s3);
        sum += __shfl_xor_sync(0xFFFFFFFF, sum, 1);
        if ((tid & 1) == 0)
            extra[((size_t)(b * HW + m0 + row)) * NB3 + blockIdx.y] = sum;
    }
}

// ------------------------------------------------------------------
// K5 fused, BN=192, BK=64: out[b][c][hw] = (attn @ V)[hw][c] + x[b][c][hw]
// attn inline from fp32 S (read once); l from K3's partials.
// 512 threads = 16 warps (4m x 4n), warp tile 32x48, 36 chunks, 2-stage.
// ------------------------------------------------------------------
__global__ __launch_bounds__(512, 1) void gemm_attnv192(
    const float* __restrict__ S,
    const float* __restrict__ part,
    const f16*  __restrict__ Vt,
    const float* __restrict__ x,
    float* __restrict__ out,
    const float* __restrict__ w1,
    const float* __restrict__ w2)
{
    extern __shared__ char smem[];
    const uint32_t sb = smem_to_u32(smem);

    constexpr int STAGE_H = (128 + 192) * ST64;     // 23040 halves per stage
    const int tid  = threadIdx.x;
    const int wid  = tid >> 5;
    const int lane = tid & 31;
    const int wm   = wid & 3;
    const int wn   = wid >> 2;
    const int m0   = blockIdx.x * BM;
    const int b    = blockIdx.z;

    const float e1 = expf(w1[0]);
    const float e2 = expf(w2[0]);
    const float inv = 1.0f / (e1 + e2);
    const float a1 = e1 * inv, a2 = e2 * inv;

    float* scs = (float*)(smem + 4 * STAGE_H);      // 92160 byte offset
    if (tid < 128) {
        const float* pp = part + ((size_t)(b * HW + m0 + tid)) * NB3;
        float l = 0.f;
        #pragma unroll
        for (int j = 0; j < NB3; j++) l += pp[j];
        scs[tid] = a1 / l;
    }

    // A loader: 128 rows x 64 fp32 per chunk; 4 threads/row, 16 fp32 each
    const int arow = tid >> 2;
    const int aq   = tid & 3;
    const float* gA = S + (size_t)b * HW * HW + (size_t)(m0 + arow) * HW + aq * 16;
    const uint32_t aoffB = 2 * (arow * ST64 + aq * 16);

    // V loader: 192 rows x 8 16B-units = 1536 units; 3 per thread
    const f16* gV[3];
    uint32_t   voff[3];
    #pragma unroll
    for (int i = 0; i < 3; i++) {
        int u = tid + 512 * i;
        int r = u >> 3, qd = u & 7;
        gV[i]   = Vt + (size_t)r * NTOT + (size_t)b * HW + qd * 8;
        voff[i] = 2 * (128 * ST64 + r * ST64 + qd * 8);
    }

    const int a_row = wm * 32 + (lane & 15);
    const int a_col = (lane >> 4) << 3;
    const int b_row = wn * 48 + ((lane >> 4) << 3) + (lane & 7);
    const int b_col = ((lane >> 3) & 1) << 3;

    float acc[2][6][4];
    #pragma unroll
    for (int i = 0; i < 2; i++)
        #pragma unroll
        for (int j = 0; j < 6; j++)
            #pragma unroll
            for (int t = 0; t < 4; t++) acc[i][j][t] = 0.f;

    const int nc = HW >> 6;   // 36

    // prologue: A chunk 0 into regs, V chunk 0 via cp.async
    float4 acur[4];
    #pragma unroll
    for (int q = 0; q < 4; q++) acur[q] = *(const float4*)(gA + q * 4);
    #pragma unroll
    for (int i = 0; i < 3; i++) CP_ASYNC16(sb + voff[i], gV[i]);
    CP_COMMIT();

    __syncthreads();   // scs ready
    const float sc_r = scs[arow];

    for (int c = 0; c < nc; c++) {
        const uint32_t stg = (c & 1) * STAGE_H;
        const bool more = (c + 1 < nc);

        // convert A(c) -> fp16 attn into stage-c A region (consumes acur)
        {
            uint32_t u[8];
            #pragma unroll
            for (int q = 0; q < 4; q++) {
                float vv[4] = {acur[q].x, acur[q].y, acur[q].z, acur[q].w};
                f16 hh[4];
                #pragma unroll
                for (int t = 0; t < 4; t++) {
                    float e = __expf(vv[t]);
                    float r = fmaxf(vv[t], 0.f);
                    hh[t] = __float2half_rn(e * sc_r + a2 * r * r);
                }
                u[2 * q]     = pack2h(hh[0], hh[1]);
                u[2 * q + 1] = pack2h(hh[2], hh[3]);
            }
            *(uint4*)(smem + 2 * stg + aoffB)      = make_uint4(u[0], u[1], u[2], u[3]);
            *(uint4*)(smem + 2 * stg + aoffB + 16) = make_uint4(u[4], u[5], u[6], u[7]);
        }

        if (more) {
            const int k0 = (c + 1) << 6;
            #pragma unroll
            for (int q = 0; q < 4; q++) acur[q] = *(const float4*)(gA + k0 + q * 4);
            const uint32_t st2 = 2 * (((c + 1) & 1) * STAGE_H);
            #pragma unroll
            for (int i = 0; i < 3; i++) CP_ASYNC16(sb + st2 + voff[i], gV[i] + k0);
            CP_COMMIT();
            CP_WAIT1();
        } else {
            CP_COMMIT();
            CP_WAIT0();
        }
        __syncthreads();      // leading

        const uint32_t sA = sb + 2 * stg;
        const uint32_t sV = sb + 2 * (stg + 128 * ST64);

        #pragma unroll
        for (int ks = 0; ks < 4; ks++) {
            const int kof = ks * 16;
            uint32_t ah[2][4], bh[3][4];
            #pragma unroll
            for (int mt = 0; mt < 2; mt++) {
                uint32_t off = 2 * ((a_row + mt * 16) * ST64 + kof + a_col);
                ldsm_x4(sA + off, ah[mt][0], ah[mt][1], ah[mt][2], ah[mt][3]);
            }
            #pragma unroll
            for (int nt2 = 0; nt2 < 3; nt2++) {
                uint32_t off = 2 * ((b_row + nt2 * 16) * ST64 + kof + b_col);
                ldsm_x4(sV + off, bh[nt2][0], bh[nt2][1], bh[nt2][2], bh[nt2][3]);
            }
            #pragma unroll
            for (int mt = 0; mt < 2; mt++)
                #pragma unroll
                for (int nt = 0; nt < 6; nt++)
                    mma_f16(acc[mt][nt], ah[mt], &bh[nt >> 1][(nt & 1) * 2]);
        }
        __syncthreads();      // trailing
    }

    constexpr int TS2 = 193;
    float* tile = (float*)smem;
    const int tr = lane >> 2;
    const int tc = (lane & 3) * 2;
    #pragma unroll
    for (int mt = 0; mt < 2; mt++) {
        #pragma unroll
        for (int nt = 0; nt < 6; nt++) {
            int rbase = wm * 32 + mt * 16 + tr;
            int cbase = wn * 48 + nt * 8 + tc;
            tile[rbase * TS2 + cbase]           = acc[mt][nt][0];
            tile[rbase * TS2 + cbase + 1]       = acc[mt][nt][1];
            tile[(rbase + 8) * TS2 + cbase]     = acc[mt][nt][2];
            tile[(rbase + 8) * TS2 + cbase + 1] = acc[mt][nt][3];
        }
    }
    __syncthreads();

    #pragma unroll
    for (int it = 0; it < 24; it++) {
        int idx = tid + 512 * it;
        int r = idx >> 6, p = idx & 63;
        size_t o = ((size_t)(b * CC + r)) * HW + m0 + 2 * p;
        float2 xv = *(const float2*)&x[o];
        float2 v;
        v.x = tile[(2 * p) * TS2 + r]     + xv.x;
        v.y = tile[(2 * p + 1) * TS2 + r] + xv.y;
        *(float2*)&out[o] = v;
    }
}

// ------------------------------------------------------------------
// launch
// ------------------------------------------------------------------
extern "C" void kernel_launch(void* const* d_in, const int* in_sizes, int n_in,
                              void* d_out, int out_size)
{
    (void)in_sizes; (void)n_in; (void)out_size;
    const float* x    = (const float*)d_in[0];
    const float* ln_w = (const float*)d_in[1];
    const float* ln_b = (const float*)d_in[2];
    const float* Wq   = (const float*)d_in[3];
    const float* Wk   = (const float*)d_in[4];
    const float* Wv   = (const float*)d_in[5];
    const float* w1   = (const float*)d_in[6];
    const float* w2   = (const float*)d_in[7];
    float* out = (float*)d_out;

    f16 *xn_h, *xn_l, *q_h, *k_h, *vt_h, *w_h;
    float *s, *pp;
    cudaGetSymbolAddress((void**)&xn_h, g_xn_h);
    cudaGetSymbolAddress((void**)&xn_l, g_xn_l);
    cudaGetSymbolAddress((void**)&q_h,  g_q_h);
    cudaGetSymbolAddress((void**)&k_h,  g_k_h);
    cudaGetSymbolAddress((void**)&vt_h, g_vt_h);
    cudaGetSymbolAddress((void**)&w_h,  g_w_h);
    cudaGetSymbolAddress((void**)&s,    g_s);
    cudaGetSymbolAddress((void**)&pp,   g_part);

    const int SM_QKV = 2 * (256 + 192) * ST64 * 2;   // 129024 (> epi 98816)
    const int SM_QK  = 2 * 256 * ST64 * 2;           // 73728
    const int SM_AV  = 128 * 193 * 4;                // 98816 (> pipe 92672)
    cudaFuncSetAttribute(gemm_qkv192,  cudaFuncAttributeMaxDynamicSharedMemorySize, SM_QKV);
    cudaFuncSetAttribute(gemm_qk128,   cudaFuncAttributeMaxDynamicSharedMemorySize, SM_QK);
    cudaFuncSetAttribute(gemm_attnv192, cudaFuncAttributeMaxDynamicSharedMemorySize, SM_AV);

    // K1: LN + transpose + split
    ln_transpose_kernel<<<dim3(HW / 32, BB), 256>>>(x, ln_w, ln_b, xn_h, xn_l);

    // Weight convert (hi only)
    wsplit_kernel<<<(3 * CC * CC + 255) / 256, 256>>>(Wq, Wk, Wv, w_h);

    // K2: Q, K, V projections in ONE launch (grid.y = weight select), BK=64
    {
        dim3 grid(NTOT / BM, 3, 1);
        gemm_qkv192<<<grid, 512, SM_QKV>>>(xn_h, xn_l, w_h, q_h, k_h, vt_h);
    }

    // K3: S = Q @ K^T per batch, 1-term fp16, 128x128, BK=64
    {
        dim3 grid(HW / BM, HW / 128, BB);
        gemm_qk128<<<grid, 256, SM_QK>>>(
            q_h, CC, (size_t)HW * CC,
            k_h, CC, (size_t)HW * CC,
            s, pp, HW, (size_t)HW * HW, CC);
    }

    // K5 fused: blend inline (S read once) + attn @ V + transpose + residual
    {
        dim3 grid(HW / BM, 1, BB);
        gemm_attnv192<<<grid, 512, SM_AV>>>(s, pp, vt_h, x, out, w1, w2);
    }
}